// round 2
// baseline (speedup 1.0000x reference)
#include <cuda_runtime.h>
#include <cuda_bf16.h>
#include <cstdint>

// Problem constants
#define Bt 64      // graphs
#define Nn 1024    // nodes per graph
#define Fd 128     // nfeat
#define Hd 256     // nhid

// ---------------- scratch (device globals: no runtime allocation allowed) ----
__device__ float g_T0[(size_t)Bt * Nn * Fd];   // adj @ embs          [B,N,F]
__device__ float g_h1[(size_t)Bt * Nn * Hd];   // relu(T0@W0 + b0)    [B,N,H]
__device__ float g_U [(size_t)Bt * Nn * Hd];   // h1 @ W1             [B,N,H]
__device__ float g_h2[(size_t)Bt * Nn * Hd];   // relu(adj@U + b1)    [B,N,H]
__device__ float g_vp[(size_t)Bt * 8 * Hd];    // partial row-0 mixes

// ---------------- PTX helpers ----------------------------------------------
__device__ __forceinline__ uint32_t smem_u32(const void* p) {
    return (uint32_t)__cvta_generic_to_shared(p);
}

__device__ __forceinline__ void ldsm_x4(uint32_t& r0, uint32_t& r1,
                                        uint32_t& r2, uint32_t& r3, uint32_t addr) {
    asm volatile("ldmatrix.sync.aligned.m8n8.x4.shared.b16 {%0,%1,%2,%3}, [%4];"
                 : "=r"(r0), "=r"(r1), "=r"(r2), "=r"(r3) : "r"(addr));
}

__device__ __forceinline__ void mma_bf16(float* c, const uint32_t* a,
                                         uint32_t b0, uint32_t b1) {
    asm volatile(
        "mma.sync.aligned.m16n8k16.row.col.f32.bf16.bf16.f32 "
        "{%0,%1,%2,%3}, {%4,%5,%6,%7}, {%8,%9}, {%0,%1,%2,%3};"
        : "+f"(c[0]), "+f"(c[1]), "+f"(c[2]), "+f"(c[3])
        : "r"(a[0]), "r"(a[1]), "r"(a[2]), "r"(a[3]), "r"(b0), "r"(b1));
}

// ---------------- split-bf16 tensor-core GEMM -------------------------------
// C[b] = A[b] @ B[b] (+bias, relu).  A: MxK row-major, B: KxN row-major.
// Batch strides in elements (0 => shared operand). Requires M%128==0,
// N%128==0, K%32==0.
// Each fp32 operand is split hi/lo bf16; acc += Ah*Bh + Ah*Bl + Al*Bh.
__global__ __launch_bounds__(256, 2)
void tgemm_kernel(const float* __restrict__ A, size_t sA,
                  const float* __restrict__ B, size_t sB,
                  float* __restrict__ C, size_t sC,
                  int M, int N, int K,
                  const float* __restrict__ bias, int doRelu)
{
    constexpr int BM = 128, BN = 128, BK = 32;
    constexpr int BKp = BK + 8;   // 40 bf16 = 80B row stride (16B aligned)

    __shared__ __align__(16) __nv_bfloat16 Ah[BM][BKp];
    __shared__ __align__(16) __nv_bfloat16 Al[BM][BKp];
    __shared__ __align__(16) __nv_bfloat16 Bh[BN][BKp];
    __shared__ __align__(16) __nv_bfloat16 Bl[BN][BKp];

    const int b = blockIdx.z;
    A += (size_t)b * sA;
    B += (size_t)b * sB;
    C += (size_t)b * sC;

    const int cRow = blockIdx.y * BM;
    const int cCol = blockIdx.x * BN;
    const int tid  = threadIdx.x;
    const int wid  = tid >> 5;
    const int lane = tid & 31;

    const int wm = (wid & 3) * 32;    // warp row offset: 4 warps along M
    const int wn = (wid >> 2) * 64;   // warp col offset: 2 warps along N

    // ldmatrix lane addressing
    const int a_lrow = lane & 15;                       // m within 16
    const int a_lcol = (lane >> 4) << 3;                // k half 0/8
    const int b_lrow = (lane & 7) | ((lane >> 4) << 3); // n within 16
    const int b_lcol = ((lane >> 3) & 1) << 3;          // k half 0/8

    // global-load mapping
    const int ldA_row = tid >> 3;          // 0..31, 4 passes stride 32
    const int ldA_col = (tid & 7) * 4;     // 0..28
    const int ldB_k   = tid >> 5;          // 0..7, 4 passes stride 8
    const int ldB_n   = lane * 4;          // 0..124

    const uint32_t Ah_b = smem_u32(&Ah[0][0]);
    const uint32_t Al_b = smem_u32(&Al[0][0]);
    const uint32_t Bh_b = smem_u32(&Bh[0][0]);
    const uint32_t Bl_b = smem_u32(&Bl[0][0]);

    float acc[2][8][4];
    #pragma unroll
    for (int i = 0; i < 2; i++)
        #pragma unroll
        for (int j = 0; j < 8; j++)
            #pragma unroll
            for (int v = 0; v < 4; v++) acc[i][j][v] = 0.f;

    for (int k0 = 0; k0 < K; k0 += BK) {
        // ---- stage A tile (split hi/lo) ----
        #pragma unroll
        for (int p = 0; p < 4; p++) {
            const int r = ldA_row + p * 32;
            float4 v = *reinterpret_cast<const float4*>(
                A + (size_t)(cRow + r) * K + k0 + ldA_col);
            float f[4] = {v.x, v.y, v.z, v.w};
            #pragma unroll
            for (int j = 0; j < 4; j++) {
                __nv_bfloat16 hi = __float2bfloat16_rn(f[j]);
                Ah[r][ldA_col + j] = hi;
                Al[r][ldA_col + j] =
                    __float2bfloat16_rn(f[j] - __bfloat162float(hi));
            }
        }
        // ---- stage B tile (transpose to [n][k], split hi/lo) ----
        #pragma unroll
        for (int p = 0; p < 4; p++) {
            const int kk = ldB_k + p * 8;
            float4 v = *reinterpret_cast<const float4*>(
                B + (size_t)(k0 + kk) * N + cCol + ldB_n);
            float f[4] = {v.x, v.y, v.z, v.w};
            #pragma unroll
            for (int j = 0; j < 4; j++) {
                __nv_bfloat16 hi = __float2bfloat16_rn(f[j]);
                Bh[ldB_n + j][kk] = hi;
                Bl[ldB_n + j][kk] =
                    __float2bfloat16_rn(f[j] - __bfloat162float(hi));
            }
        }
        __syncthreads();

        // ---- MMA over the staged tile ----
        #pragma unroll
        for (int ks = 0; ks < BK / 16; ks++) {
            uint32_t ah[2][4], al[2][4];
            #pragma unroll
            for (int mf = 0; mf < 2; mf++) {
                const uint32_t off =
                    ((wm + mf * 16 + a_lrow) * BKp + ks * 16 + a_lcol) * 2;
                ldsm_x4(ah[mf][0], ah[mf][1], ah[mf][2], ah[mf][3], Ah_b + off);
                ldsm_x4(al[mf][0], al[mf][1], al[mf][2], al[mf][3], Al_b + off);
            }
            #pragma unroll
            for (int g = 0; g < 4; g++) {   // 2 n-frags per group
                const uint32_t off =
                    ((wn + g * 16 + b_lrow) * BKp + ks * 16 + b_lcol) * 2;
                uint32_t bh[4], bl[4];
                ldsm_x4(bh[0], bh[1], bh[2], bh[3], Bh_b + off);
                ldsm_x4(bl[0], bl[1], bl[2], bl[3], Bl_b + off);
                #pragma unroll
                for (int n2 = 0; n2 < 2; n2++) {
                    const int nf = g * 2 + n2;
                    #pragma unroll
                    for (int mf = 0; mf < 2; mf++) {
                        mma_bf16(acc[mf][nf], ah[mf], bh[n2 * 2], bh[n2 * 2 + 1]); // hi*hi
                        mma_bf16(acc[mf][nf], ah[mf], bl[n2 * 2], bl[n2 * 2 + 1]); // hi*lo
                        mma_bf16(acc[mf][nf], al[mf], bh[n2 * 2], bh[n2 * 2 + 1]); // lo*hi
                    }
                }
            }
        }
        __syncthreads();
    }

    // ---- epilogue: bias + relu, fp32 stores ----
    const int gid = lane >> 2;
    const int tig = lane & 3;
    #pragma unroll
    for (int mf = 0; mf < 2; mf++) {
        #pragma unroll
        for (int nf = 0; nf < 8; nf++) {
            const int col = cCol + wn + nf * 8 + tig * 2;
            float v0 = acc[mf][nf][0], v1 = acc[mf][nf][1];
            float v2 = acc[mf][nf][2], v3 = acc[mf][nf][3];
            if (bias) {
                const float bz0 = bias[col], bz1 = bias[col + 1];
                v0 += bz0; v1 += bz1; v2 += bz0; v3 += bz1;
            }
            if (doRelu) {
                v0 = fmaxf(v0, 0.f); v1 = fmaxf(v1, 0.f);
                v2 = fmaxf(v2, 0.f); v3 = fmaxf(v3, 0.f);
            }
            const int r0 = cRow + wm + mf * 16 + gid;
            *reinterpret_cast<float2*>(C + (size_t)r0 * N + col) =
                make_float2(v0, v1);
            *reinterpret_cast<float2*>(C + (size_t)(r0 + 8) * N + col) =
                make_float2(v2, v3);
        }
    }
}

// ---------------- layer-3 row-0 mix -----------------------------------------
__global__ void rowmix_kernel(const float* __restrict__ adj,
                              const float* __restrict__ h2,
                              float* __restrict__ vp)
{
    const int c = blockIdx.x;     // 8 chunks of 128 nodes
    const int b = blockIdx.y;
    const int h = threadIdx.x;    // 256 threads

    const float* ar = adj + (size_t)b * Nn * Nn + c * 128;
    const float* hb = h2  + (size_t)b * Nn * Hd + (size_t)(c * 128) * Hd;

    float acc = 0.f;
    #pragma unroll 8
    for (int n = 0; n < 128; n++)
        acc = fmaf(ar[n], hb[(size_t)n * Hd + h], acc);

    vp[((size_t)b * 8 + c) * Hd + h] = acc;
}

// ---------------- head ------------------------------------------------------
__global__ void head_kernel(const float* __restrict__ vp,
                            const float* __restrict__ W2,
                            const float* __restrict__ b2,
                            const float* __restrict__ Wl,
                            const float* __restrict__ bl,
                            float* __restrict__ out)
{
    const int b   = blockIdx.x;
    const int tid = threadIdx.x;

    __shared__ float vsh[Hd];
    __shared__ float tsh[Hd];

    float acc = 0.f;
    #pragma unroll
    for (int c = 0; c < 8; c++)
        acc += vp[((size_t)b * 8 + c) * Hd + tid];
    vsh[tid] = acc;
    __syncthreads();

    float t = b2[tid];
    #pragma unroll 8
    for (int k = 0; k < Hd; k++)
        t = fmaf(vsh[k], W2[(size_t)k * Hd + tid], t);
    tsh[tid] = fmaxf(t, 0.f);
    __syncthreads();

    if (tid < Fd) {
        float o = bl[tid];
        #pragma unroll 8
        for (int h = 0; h < Hd; h++)
            o = fmaf(tsh[h], Wl[(size_t)h * Fd + tid], o);
        out[(size_t)b * Fd + tid] = o;
    }
}

// ---------------------------------------------------------------------------
extern "C" void kernel_launch(void* const* d_in, const int* in_sizes, int n_in,
                              void* d_out, int out_size)
{
    const float* embs = (const float*)d_in[0];   // [B,N,F]
    const float* adj  = (const float*)d_in[1];   // [B,N,N]
    const float* W0   = (const float*)d_in[2];   // [F,H]
    const float* b0   = (const float*)d_in[3];   // [H]
    const float* W1   = (const float*)d_in[4];   // [H,H]
    const float* b1   = (const float*)d_in[5];   // [H]
    const float* W2   = (const float*)d_in[6];   // [H,H]
    const float* b2   = (const float*)d_in[7];   // [H]
    const float* Wl   = (const float*)d_in[8];   // [H,F]
    const float* bl   = (const float*)d_in[9];   // [F]
    float* out = (float*)d_out;                  // [B,F]

    float *T0, *h1, *U, *h2, *vp;
    cudaGetSymbolAddress((void**)&T0, g_T0);
    cudaGetSymbolAddress((void**)&h1, g_h1);
    cudaGetSymbolAddress((void**)&U,  g_U);
    cudaGetSymbolAddress((void**)&h2, g_h2);
    cudaGetSymbolAddress((void**)&vp, g_vp);

    dim3 blk(256);

    // G0: T0 = adj @ embs        [1024x1024]@[1024x128]
    tgemm_kernel<<<dim3(Fd/128, Nn/128, Bt), blk>>>(
        adj, (size_t)Nn * Nn, embs, (size_t)Nn * Fd, T0, (size_t)Nn * Fd,
        Nn, Fd, Nn, nullptr, 0);

    // G1: h1 = relu(T0 @ W0 + b0)   [1024x128]@[128x256]
    tgemm_kernel<<<dim3(Hd/128, Nn/128, Bt), blk>>>(
        T0, (size_t)Nn * Fd, W0, 0, h1, (size_t)Nn * Hd,
        Nn, Hd, Fd, b0, 1);

    // G2: U = h1 @ W1               [1024x256]@[256x256]
    tgemm_kernel<<<dim3(Hd/128, Nn/128, Bt), blk>>>(
        h1, (size_t)Nn * Hd, W1, 0, U, (size_t)Nn * Hd,
        Nn, Hd, Hd, nullptr, 0);

    // G3: h2 = relu(adj @ U + b1)   [1024x1024]@[1024x256]
    tgemm_kernel<<<dim3(Hd/128, Nn/128, Bt), blk>>>(
        adj, (size_t)Nn * Nn, U, (size_t)Nn * Hd, h2, (size_t)Nn * Hd,
        Nn, Hd, Nn, b1, 1);

    // G4: vp[b,c,:] = adj[b,0,chunk c] @ h2[b,chunk c,:]
    rowmix_kernel<<<dim3(8, Bt), dim3(Hd)>>>(adj, h2, vp);

    // G5: out = relu(v@W2+b2) @ Wl + bl
    head_kernel<<<dim3(Bt), dim3(Hd)>>>(vp, W2, b2, Wl, bl, out);
}